// round 7
// baseline (speedup 1.0000x reference)
#include <cuda_runtime.h>

// RecallCELoss — FINAL.
//
// Reference math:
//   loss = -mean((1 - recall) * nc * log(pc)) with pc = ones  =>  log(pc) = 0
// so the output is identically the constant 0.0f for ANY input (bit pattern
// 0x00000000). The entire computation constant-folds; benchmark cost is purely
// the dispatch of ONE graph node per replay (0-node captures fail the harness,
// so one node is the hard minimum).
//
// Node-type dispatch floor, measured on this harness (sm_103a, graph replay):
//   MEMSET node : 3.20 / 3.94 us  <-- floor (this kernel; ~±0.4us container noise)
//   kernel node : 4.54 us
//   memcpy node : 5.76 us         (copy-engine doorbell + fence is heavier)
//
// Writing zero bytes into a float buffer is bit-exact IEEE 0.0f => rel_err = 0
// exactly. No allocation, no sync — legal graph capture. Remaining time is
// fixed graph-replay dispatch latency, not kernel-controllable.

extern "C" void kernel_launch(void* const* d_in, const int* in_sizes, int n_in,
                              void* d_out, int out_size) {
    (void)d_in; (void)in_sizes; (void)n_in;
    cudaMemsetAsync(d_out, 0, (size_t)out_size * sizeof(float), 0);
}

// round 9
// speedup vs baseline: 1.2475x; 1.2475x over previous
#include <cuda_runtime.h>

// RecallCELoss — FINAL.
//
// Reference math:
//   loss = -mean((1 - recall) * nc * log(pc)) with pc = ones  =>  log(pc) = 0
// so the output is identically the constant 0.0f for ANY input (bit pattern
// 0x00000000). The entire computation constant-folds to a 4-byte zero write;
// benchmark cost is purely the dispatch of ONE graph node per replay (0-node
// captures fail the harness, so one node is the hard minimum).
//
// Node-type dispatch sweep, measured on this harness (sm_103a, graph replay):
//   MEMSET node : 3.20 / 3.94 / 4.03 us  <-- floor; identical binary, so the
//                                            spread is container noise (~±0.4us)
//   kernel node : 4.54 us
//   memcpy node : 5.76 us                (copy-engine doorbell + fence heavier)
//
// Writing zero bytes into a float buffer is bit-exact IEEE 0.0f => rel_err = 0
// exactly. Cannot shrink below 4 bytes (d_out is poisoned to 0xAA; a partial
// write would leave a nonzero float). No allocation, no sync — legal graph
// capture. Remaining time is fixed graph-replay dispatch latency, not
// kernel-controllable: zero predicted headroom from any further change.

extern "C" void kernel_launch(void* const* d_in, const int* in_sizes, int n_in,
                              void* d_out, int out_size) {
    (void)d_in; (void)in_sizes; (void)n_in;
    cudaMemsetAsync(d_out, 0, (size_t)out_size * sizeof(float), 0);
}